// round 1
// baseline (speedup 1.0000x reference)
#include <cuda_runtime.h>

// SSD detection post-processing.
// B=128 batches, N=8732 anchors, C=21 classes, top_k=keep_top_k=200.
// Pipeline: K1 decode+softmax -> K2 per-(b,class) top-200 + greedy NMS ->
//           K3 per-batch global top-200 + per-class compaction into output.

#define NB   128
#define NA   8732
#define NCLS 21
#define NC1  20     // foreground classes
#define TK   200    // per-class candidate cap == global keep_top_k

// ---- scratch (device globals; no allocation allowed) ----
__device__ float4       g_boxes[NB * NA];                      // decoded boxes
__device__ unsigned int g_umap[(size_t)NB * NC1 * NA];         // order-mapped thresholded scores
__device__ float        g_kscore[NB * NC1 * TK];               // kept scores after NMS (0 if dropped)
__device__ float4       g_kbox[NB * NC1 * TK];                 // kept boxes after NMS (0 if dropped)

// orderable map: ascending uint <=> ascending float
__device__ __forceinline__ unsigned f2u(float f) {
    unsigned b = __float_as_uint(f);
    return (b & 0x80000000u) ? ~b : (b | 0x80000000u);
}
__device__ __forceinline__ float u2f(unsigned u) {
    unsigned b = (u & 0x80000000u) ? (u & 0x7FFFFFFFu) : ~u;
    return __uint_as_float(b);
}

// ============================================================================
// K1: decode boxes + softmax -> order-mapped per-class scores
// grid: (ceil(NA/256), NB), 256 threads
// ============================================================================
__global__ __launch_bounds__(256) void k_prep(const float* __restrict__ loc,
                                              const float* __restrict__ conf,
                                              const float* __restrict__ dbox)
{
    __shared__ float s_conf[256 * NCLS];
    int b   = blockIdx.y;
    int n0  = blockIdx.x * 256;
    int tid = threadIdx.x;

    int nrow = NA - n0; if (nrow > 256) nrow = 256;
    int cnt  = nrow * NCLS;
    size_t base = ((size_t)b * NA + n0) * NCLS;
    for (int i = tid; i < cnt; i += 256) s_conf[i] = conf[base + i];
    __syncthreads();

    int n = n0 + tid;
    if (n >= NA) return;

    // ---- decode (match reference rounding: no FMA contraction) ----
    float4 l = reinterpret_cast<const float4*>(loc)[b * NA + n];
    float4 d = reinterpret_cast<const float4*>(dbox)[n];
    float cx = __fadd_rn(d.x, __fmul_rn(__fmul_rn(l.x, 0.1f), d.z));
    float cy = __fadd_rn(d.y, __fmul_rn(__fmul_rn(l.y, 0.1f), d.w));
    float w  = __fmul_rn(d.z, expf(__fmul_rn(l.z, 0.2f)));
    float h  = __fmul_rn(d.w, expf(__fmul_rn(l.w, 0.2f)));
    float x1 = __fsub_rn(cx, __fmul_rn(w, 0.5f));
    float y1 = __fsub_rn(cy, __fmul_rn(h, 0.5f));
    float x2 = __fadd_rn(x1, w);   // maxs = (unclipped) mins + wh
    float y2 = __fadd_rn(y1, h);
    x1 = fminf(fmaxf(x1, 0.f), 1.f);
    y1 = fminf(fmaxf(y1, 0.f), 1.f);
    x2 = fminf(fmaxf(x2, 0.f), 1.f);
    y2 = fminf(fmaxf(y2, 0.f), 1.f);
    g_boxes[b * NA + n] = make_float4(x1, y1, x2, y2);

    // ---- softmax over 21 classes ----
    const float* cv = &s_conf[tid * NCLS];
    float m = cv[0];
#pragma unroll
    for (int c = 1; c < NCLS; c++) m = fmaxf(m, cv[c]);
    float e[NCLS];
    float s = 0.f;
#pragma unroll
    for (int c = 0; c < NCLS; c++) { e[c] = expf(__fsub_rn(cv[c], m)); s = __fadd_rn(s, e[c]); }
#pragma unroll
    for (int c = 1; c < NCLS; c++) {
        float p  = __fdiv_rn(e[c], s);
        float sv = (p > 0.01f) ? p : -1.0f;           // threshold fold-in (jax: where(>thr, s, -1))
        g_umap[((size_t)b * NC1 + (c - 1)) * NA + n] = f2u(sv);
    }
}

// ============================================================================
// K2: per (batch,class): exact top-200 (radix select + bitonic) + greedy NMS
// grid: NB*NC1 blocks, 256 threads
// ============================================================================
__global__ __launch_bounds__(256) void k_nms()
{
    __shared__ __align__(16) unsigned s_u[NA];        // score row (reused for NMS arrays later)
    __shared__ unsigned long long    s_cand[256];     // (value<<32)|(~index) keys
    __shared__ unsigned              s_hist[256];
    __shared__ unsigned              s_info[4];

    int task = blockIdx.x;           // b*20 + c
    int b    = task / NC1;
    int tid  = threadIdx.x;

    const unsigned* urow = &g_umap[(size_t)task * NA];
    for (int i = tid; i < NA; i += 256) s_u[i] = urow[i];

    // ---- 4-level radix select: exact value of 200th-largest ----
    unsigned prefix = 0, k = TK;
    for (int level = 0; level < 4; level++) {
        int shift = 24 - 8 * level;
        unsigned mask = level ? (0xFFFFFFFFu << (32 - 8 * level)) : 0u;
        s_hist[tid] = 0;
        __syncthreads();                               // also covers initial s_u fill
        for (int i = tid; i < NA; i += 256) {
            unsigned u = s_u[i];
            if ((u & mask) == prefix) atomicAdd(&s_hist[(u >> shift) & 0xFFu], 1u);
        }
        __syncthreads();
        if (tid == 0) {
            unsigned cum = 0; int d = 255;
            for (;; d--) {
                unsigned nc2 = cum + s_hist[d];
                if (nc2 >= k || d == 0) break;
                cum = nc2;
            }
            s_info[0] = prefix | ((unsigned)d << shift);
            s_info[1] = k - cum;
        }
        __syncthreads();
        prefix = s_info[0];
        k      = s_info[1];
        __syncthreads();
    }
    unsigned ucut = prefix, keq = k;                   // strictly-greater count = TK - keq

    // ---- gather exactly 200 candidates ----
    if (tid == 0) { s_info[2] = 0; s_info[3] = 0; }
    __syncthreads();
    for (int i = tid; i < NA; i += 256) {
        unsigned u = s_u[i];
        if (u > ucut) {
            unsigned p = atomicAdd(&s_info[2], 1u);
            s_cand[p] = ((unsigned long long)u << 32) | (0xFFFFFFFFu - (unsigned)i);
        }
    }
    __syncthreads();
    unsigned ngt = s_info[2];
    for (int i = tid; i < NA; i += 256) {
        unsigned u = s_u[i];
        if (u == ucut) {
            unsigned p = atomicAdd(&s_info[3], 1u);
            if (p < keq)
                s_cand[ngt + p] = ((unsigned long long)u << 32) | (0xFFFFFFFFu - (unsigned)i);
        }
    }
    __syncthreads();
    if (tid >= TK) s_cand[tid] = 0ULL;                 // pad to 256
    __syncthreads();

    // ---- bitonic sort 256 keys, descending (value desc, index asc on ties) ----
    for (int kk = 2; kk <= 256; kk <<= 1) {
        for (int j = kk >> 1; j > 0; j >>= 1) {
            int ixj = tid ^ j;
            if (ixj > tid) {
                unsigned long long a = s_cand[tid], c2 = s_cand[ixj];
                bool dir = ((tid & kk) == 0);
                if ((a < c2) == dir) { s_cand[tid] = c2; s_cand[ixj] = a; }
            }
            __syncthreads();
        }
    }

    // ---- stage candidates (overlay NMS arrays on s_u, done with raw scores) ----
    float*  sc    = reinterpret_cast<float*>(s_u);
    float4* bx    = reinterpret_cast<float4*>(s_u + 256);         // 16B aligned
    float*  ar    = reinterpret_cast<float*>(s_u + 256 + 4 * TK);
    int*    alive = reinterpret_cast<int*>(s_u + 256 + 4 * TK + TK);
    if (tid < TK) {
        unsigned long long key = s_cand[tid];
        unsigned u   = (unsigned)(key >> 32);
        unsigned idx = 0xFFFFFFFFu - (unsigned)key;
        float v  = u2f(u);
        float4 bb = g_boxes[b * NA + (int)idx];
        sc[tid] = v;
        bx[tid] = bb;
        ar[tid] = __fmul_rn(__fsub_rn(bb.z, bb.x), __fsub_rn(bb.w, bb.y));
        alive[tid] = (v > 0.01f) ? 1 : 0;
    }
    __syncthreads();

    // ---- greedy NMS: suppress j>i with !(iou<=0.45) (NaN suppresses, like ref) ----
    for (int i = 0; i < TK; i++) {
        if (alive[i] && tid > i && tid < TK && alive[tid]) {
            float xx1 = fmaxf(bx[tid].x, bx[i].x);
            float yy1 = fmaxf(bx[tid].y, bx[i].y);
            float xx2 = fminf(bx[tid].z, bx[i].z);
            float yy2 = fminf(bx[tid].w, bx[i].w);
            float iw = fmaxf(__fsub_rn(xx2, xx1), 0.f);
            float ih = fmaxf(__fsub_rn(yy2, yy1), 0.f);
            float inter = __fmul_rn(iw, ih);
            float denom = __fsub_rn(__fadd_rn(ar[tid], ar[i]), inter);
            float iou   = __fdiv_rn(inter, denom);
            if (!(iou <= 0.45f)) alive[tid] = 0;
        }
        __syncthreads();
    }

    if (tid < TK) {
        int o = task * TK + tid;
        bool kp = (alive[tid] != 0);
        g_kscore[o] = kp ? sc[tid] : 0.f;
        g_kbox[o]   = kp ? bx[tid] : make_float4(0.f, 0.f, 0.f, 0.f);
    }
}

// ============================================================================
// K3: per batch: global top-200 over 4000 kept scores, per-class compaction
// grid: NB blocks, 256 threads
// ============================================================================
__global__ __launch_bounds__(256) void k_final(float* __restrict__ out)
{
    __shared__ unsigned long long s_key[4096];
    int b   = blockIdx.x;
    int tid = threadIdx.x;

    const float* ks = &g_kscore[b * NC1 * TK];
    for (int i = tid; i < 4096; i += 256) {
        unsigned long long key = 0ULL;
        if (i < NC1 * TK) {
            unsigned u = f2u(ks[i]);
            key = ((unsigned long long)u << 32) | (0xFFFFFFFFu - (unsigned)i);
        }
        s_key[i] = key;
    }

    // zero this batch's output slab (output poisoned by harness)
    float* ob = out + (size_t)b * NCLS * TK * 5;
    for (int i = tid; i < NCLS * TK * 5; i += 256) ob[i] = 0.f;
    __syncthreads();

    // bitonic sort 4096 keys descending
    for (int kk = 2; kk <= 4096; kk <<= 1) {
        for (int j = kk >> 1; j > 0; j >>= 1) {
            for (int i = tid; i < 4096; i += 256) {
                int ixj = i ^ j;
                if (ixj > i) {
                    unsigned long long a = s_key[i], c2 = s_key[ixj];
                    bool dir = ((i & kk) == 0);
                    if ((a < c2) == dir) { s_key[i] = c2; s_key[ixj] = a; }
                }
            }
            __syncthreads();
        }
    }

    // top-200: for each positive entry, rank within its class among earlier
    // global ranks -> row position; write (score, x1,y1,x2,y2)
    if (tid < TK) {
        unsigned long long key = s_key[tid];
        unsigned u = (unsigned)(key >> 32);
        if (u > 0x80000000u) {                         // score > 0
            unsigned flat = 0xFFFFFFFFu - (unsigned)key;
            int cls = (int)(flat / TK);                // 0..19
            int pos = 0;
            for (int g = 0; g < tid; g++) {
                unsigned long long k2 = s_key[g];
                unsigned u2 = (unsigned)(k2 >> 32);
                if (u2 > 0x80000000u) {
                    unsigned f2 = 0xFFFFFFFFu - (unsigned)k2;
                    if ((int)(f2 / TK) == cls) pos++;
                }
            }
            float v   = __uint_as_float(u & 0x7FFFFFFFu);
            float4 bb = g_kbox[b * NC1 * TK + flat];
            float* row = ob + ((cls + 1) * TK + pos) * 5;
            row[0] = v;
            row[1] = bb.x; row[2] = bb.y; row[3] = bb.z; row[4] = bb.w;
        }
    }
}

// ============================================================================
extern "C" void kernel_launch(void* const* d_in, const int* in_sizes, int n_in,
                              void* d_out, int out_size)
{
    const float* loc  = (const float*)d_in[0];   // [B, N, 4]
    const float* conf = (const float*)d_in[1];   // [B, N, C]
    const float* dbox = (const float*)d_in[2];   // [N, 4]
    float* out = (float*)d_out;                  // [B, C, 200, 5]

    k_prep <<<dim3((NA + 255) / 256, NB), 256>>>(loc, conf, dbox);
    k_nms  <<<NB * NC1, 256>>>();
    k_final<<<NB, 256>>>(out);
}